// round 2
// baseline (speedup 1.0000x reference)
#include <cuda_runtime.h>
#include <cstdint>

// ============================================================================
// scores[b,l] = sum_d tanh( (enc[b,l,:] @ W1_e)[d] + dec_proj[b,d] + b1[d] ) * w2[d]
// out = softmax(scores, axis=-1).  B=32, LIN=2048, E=D=512, nd=1024.
//
// sm_103 (plain target: no tcgen05) -> mma.sync.aligned.m16n8k8 tf32 GEMM,
// fused tanh + dot(w2) epilogue, cp.async 3-stage pipeline, XOR-swizzled smem.
// ============================================================================

// Scratch (device globals: no allocation allowed)
__device__ __align__(16) float g_W1T[512 * 512];    // W1_e^T, [d][k], tf32-rounded
__device__ __align__(16) float g_dpp[128 * 512];    // dec_proj split-K partials
__device__ __align__(16) float g_scores[32 * 2048]; // pre-softmax scores

// ---------------------------------------------------------------------------
// helpers
// ---------------------------------------------------------------------------
__device__ __forceinline__ void cp_async16(void* sdst, const void* gsrc) {
    uint32_t s;
    asm("{ .reg .u64 t; cvta.to.shared.u64 t, %1; cvt.u32.u64 %0, t; }" : "=r"(s) : "l"(sdst));
    asm volatile("cp.async.cg.shared.global [%0], [%1], 16;" :: "r"(s), "l"(gsrc) : "memory");
}
#define CP_COMMIT() asm volatile("cp.async.commit_group;" ::: "memory")
#define CP_WAIT(n)  asm volatile("cp.async.wait_group %0;" :: "n"(n) : "memory")

__device__ __forceinline__ uint32_t f2tf32(float v) {
    uint32_t r;
    asm("cvt.rna.tf32.f32 %0, %1;" : "=r"(r) : "f"(v));
    return r;
}
__device__ __forceinline__ float tanh_fast(float x) {
    float t;
    asm("tanh.approx.f32 %0, %1;" : "=f"(t) : "f"(x));
    return t;
}
__device__ __forceinline__ void mma_tf32(float c[4], const uint32_t a[4], const uint32_t b[2]) {
    asm volatile(
        "mma.sync.aligned.m16n8k8.row.col.f32.tf32.tf32.f32 "
        "{%0,%1,%2,%3}, {%4,%5,%6,%7}, {%8,%9}, {%0,%1,%2,%3};"
        : "+f"(c[0]), "+f"(c[1]), "+f"(c[2]), "+f"(c[3])
        : "r"(a[0]), "r"(a[1]), "r"(a[2]), "r"(a[3]), "r"(b[0]), "r"(b[1]));
}

// XOR swizzle: 128B rows of 8 x 16B blocks; block' = block ^ (row & 7).
// Fragment LDS (fixed block, rows=quad 0..7, 4B lanes within block) is then
// bank-conflict-free: bank = ((blk^row)*4 + qlane), all 32 distinct.
__device__ __forceinline__ uint32_t swz_off(int row, int blk, int qlane) {
    return (uint32_t)(row * 128 + ((blk ^ (row & 7)) << 4) + qlane * 4);
}

// ---------------------------------------------------------------------------
// Kernel 0: transpose W1_e (rows 1024..1535 of W1, [512k x 512d]) into
// g_W1T[d][k], pre-rounded to tf32 (rna) so the B operand needs no cvt.
// ---------------------------------------------------------------------------
__global__ void w1t_transpose_kernel(const float* __restrict__ W1) {
    __shared__ float tile[32][33];
    int tx = threadIdx.x, ty = threadIdx.y;
    int d0 = blockIdx.x * 32, k0 = blockIdx.y * 32;
#pragma unroll
    for (int j = 0; j < 32; j += 8)
        tile[ty + j][tx] = W1[(size_t)(1024 + k0 + ty + j) * 512 + d0 + tx];
    __syncthreads();
#pragma unroll
    for (int j = 0; j < 32; j += 8)
        g_W1T[(size_t)(d0 + ty + j) * 512 + k0 + tx] =
            __uint_as_float(f2tf32(tile[tx][ty + j]));
}

// ---------------------------------------------------------------------------
// Kernel 1: dec_proj split-K partials (fp32 exact). block = b*4+q, 512 thr = d.
// ---------------------------------------------------------------------------
__global__ void dec_proj_kernel(const float* __restrict__ dh, const float* __restrict__ W1) {
    __shared__ float sdf[256];
    int bq = blockIdx.x;
    int b = bq >> 2, q = bq & 3;
    int d = threadIdx.x;
    if (d < 256) sdf[d] = dh[b * 1024 + q * 256 + d];
    __syncthreads();
    const float* w = W1 + (size_t)(q * 256) * 512 + d;
    float a0 = 0.f, a1 = 0.f, a2 = 0.f, a3 = 0.f;
#pragma unroll 4
    for (int k = 0; k < 256; k += 4) {
        a0 = fmaf(sdf[k + 0], w[(size_t)(k + 0) * 512], a0);
        a1 = fmaf(sdf[k + 1], w[(size_t)(k + 1) * 512], a1);
        a2 = fmaf(sdf[k + 2], w[(size_t)(k + 2) * 512], a2);
        a3 = fmaf(sdf[k + 3], w[(size_t)(k + 3) * 512], a3);
    }
    g_dpp[(size_t)bq * 512 + d] = (a0 + a1) + (a2 + a3);
}

// ---------------------------------------------------------------------------
// Kernel 2: fused tf32 GEMM + tanh + dot(w2).
// 512 CTAs x 256 thr (8 warps, 2m x 4n; warp tile 64x32).
// CTA = 128 rows; loops 4 n-chunks of 128 cols; K streamed in 16 tiles of 32.
// ---------------------------------------------------------------------------
static constexpr uint32_t AUX_SZ   = 8192;
static constexpr uint32_t STAGE_SZ = 32768; // A 16KB + B 16KB
static constexpr uint32_t SMEM_MAIN = AUX_SZ + 3 * STAGE_SZ; // 106496

__global__ void __launch_bounds__(256, 2)
attn_main_kernel(const float* __restrict__ enc, const float* __restrict__ b1,
                 const float* __restrict__ w2) {
    extern __shared__ char sm[];
    float* add_s = (float*)sm;                 // 512
    float* w2_s  = (float*)(sm + 2048);        // 512
    float* spart = (float*)(sm + 4096);        // 4 x 128
    float* ssum  = (float*)(sm + 6144);        // 128
    char*  stages = sm + AUX_SZ;

    const int tid  = threadIdx.x;
    const int wid  = tid >> 5, lane = tid & 31;
    const int wm   = wid & 1, wn = wid >> 1;       // warp grid 2m x 4n
    const int quad = lane >> 2, qlane = lane & 3;

    const int b  = blockIdx.x >> 4;
    const int l0 = (blockIdx.x & 15) << 7;
    const size_t row0 = (size_t)(b * 2048 + l0);
    const float* gA = enc + row0 * 512;

    for (int d = tid; d < 512; d += 256) {
        float s0 = g_dpp[(size_t)(b * 4 + 0) * 512 + d] + g_dpp[(size_t)(b * 4 + 1) * 512 + d];
        float s1 = g_dpp[(size_t)(b * 4 + 2) * 512 + d] + g_dpp[(size_t)(b * 4 + 3) * 512 + d];
        add_s[d] = s0 + s1 + b1[d];
        w2_s[d]  = w2[d];
    }
    if (tid < 128) ssum[tid] = 0.f;
    __syncthreads();

    // loader lane mapping: 256 threads x 16B; tile = 128 rows x 128B, 4 passes
    const int ldr = tid >> 3;       // 0..31 (row within pass)
    const int ldf = tid & 7;        // 16B block within row

    for (int nc = 0; nc < 4; nc++) {
        const float* gB = g_W1T + (size_t)(nc * 128) * 512;

        // ---- pipeline prologue: 3 k-tiles in flight ----
#pragma unroll
        for (int s = 0; s < 3; s++) {
            char* sA = stages + s * STAGE_SZ;
            char* sB = sA + 16384;
#pragma unroll
            for (int p = 0; p < 4; p++) {
                int r = ldr + p * 32;
                cp_async16(sA + swz_off(r, ldf, 0), gA + (size_t)r * 512 + s * 32 + ldf * 4);
                cp_async16(sB + swz_off(r, ldf, 0), gB + (size_t)r * 512 + s * 32 + ldf * 4);
            }
            CP_COMMIT();
        }

        float acc[4][4][4];
#pragma unroll
        for (int i = 0; i < 4; i++)
#pragma unroll
            for (int j = 0; j < 4; j++)
#pragma unroll
                for (int k = 0; k < 4; k++) acc[i][j][k] = 0.f;

        for (int kt = 0; kt < 16; kt++) {
            CP_WAIT(2);
            __syncthreads();
            const char* sA = stages + (kt % 3) * STAGE_SZ;
            const char* sB = sA + 16384;

#pragma unroll 1
            for (int ks = 0; ks < 4; ks++) {
                const int blk0 = ks * 2;
                uint32_t afr[4][4], bfr[4][2];
#pragma unroll
                for (int mf = 0; mf < 4; mf++) {
                    int r0 = wm * 64 + mf * 16 + quad;
                    afr[mf][0] = f2tf32(*(const float*)(sA + swz_off(r0,     blk0,     qlane)));
                    afr[mf][2] = f2tf32(*(const float*)(sA + swz_off(r0,     blk0 + 1, qlane)));
                    afr[mf][1] = f2tf32(*(const float*)(sA + swz_off(r0 + 8, blk0,     qlane)));
                    afr[mf][3] = f2tf32(*(const float*)(sA + swz_off(r0 + 8, blk0 + 1, qlane)));
                }
#pragma unroll
                for (int nf = 0; nf < 4; nf++) {
                    int nr = wn * 32 + nf * 8 + quad;
                    bfr[nf][0] = __float_as_uint(*(const float*)(sB + swz_off(nr, blk0,     qlane)));
                    bfr[nf][1] = __float_as_uint(*(const float*)(sB + swz_off(nr, blk0 + 1, qlane)));
                }
#pragma unroll
                for (int mf = 0; mf < 4; mf++)
#pragma unroll
                    for (int nf = 0; nf < 4; nf++)
                        mma_tf32(acc[mf][nf], afr[mf], bfr[nf]);
            }
            __syncthreads();

            int ktn = kt + 3;
            if (ktn < 16) {
                char* dA = stages + (kt % 3) * STAGE_SZ;
                char* dB = dA + 16384;
#pragma unroll
                for (int p = 0; p < 4; p++) {
                    int r = ldr + p * 32;
                    cp_async16(dA + swz_off(r, ldf, 0), gA + (size_t)r * 512 + ktn * 32 + ldf * 4);
                    cp_async16(dB + swz_off(r, ldf, 0), gB + (size_t)r * 512 + ktn * 32 + ldf * 4);
                }
            }
            CP_COMMIT();
        }
        CP_WAIT(0);

        // ---- epilogue for this n-chunk: tanh(acc + add) * w2, reduce ----
        float sacc[4][2];
#pragma unroll
        for (int mf = 0; mf < 4; mf++) { sacc[mf][0] = 0.f; sacc[mf][1] = 0.f; }
#pragma unroll
        for (int mf = 0; mf < 4; mf++) {
#pragma unroll
            for (int nf = 0; nf < 4; nf++) {
                int c0 = nc * 128 + wn * 32 + nf * 8 + qlane * 2;
                float a0 = add_s[c0], a1 = add_s[c0 + 1];
                float v0 = w2_s[c0],  v1 = w2_s[c0 + 1];
                sacc[mf][0] = fmaf(tanh_fast(acc[mf][nf][0] + a0), v0, sacc[mf][0]);
                sacc[mf][0] = fmaf(tanh_fast(acc[mf][nf][1] + a1), v1, sacc[mf][0]);
                sacc[mf][1] = fmaf(tanh_fast(acc[mf][nf][2] + a0), v0, sacc[mf][1]);
                sacc[mf][1] = fmaf(tanh_fast(acc[mf][nf][3] + a1), v1, sacc[mf][1]);
            }
        }
#pragma unroll
        for (int mf = 0; mf < 4; mf++) {
#pragma unroll
            for (int off = 1; off < 4; off <<= 1) {
                sacc[mf][0] += __shfl_xor_sync(0xffffffffu, sacc[mf][0], off);
                sacc[mf][1] += __shfl_xor_sync(0xffffffffu, sacc[mf][1], off);
            }
        }
        if (qlane == 0) {
#pragma unroll
            for (int mf = 0; mf < 4; mf++) {
                int r = wm * 64 + mf * 16 + quad;
                spart[wn * 128 + r]     = sacc[mf][0];
                spart[wn * 128 + r + 8] = sacc[mf][1];
            }
        }
        __syncthreads();
        if (tid < 128)
            ssum[tid] += spart[tid] + spart[128 + tid] + spart[256 + tid] + spart[384 + tid];
        __syncthreads();
    }

    if (tid < 128) g_scores[row0 + tid] = ssum[tid];
}

// ---------------------------------------------------------------------------
// Kernel 3: row softmax over 2048. 32 blocks x 256 threads.
// ---------------------------------------------------------------------------
__global__ void softmax_kernel(float* __restrict__ out) {
    __shared__ float red[256];
    int b = blockIdx.x, t = threadIdx.x;
    float v[8];
    float vmax = -1e30f;
#pragma unroll
    for (int j = 0; j < 8; j++) {
        v[j] = g_scores[b * 2048 + j * 256 + t];
        vmax = fmaxf(vmax, v[j]);
    }
    red[t] = vmax; __syncthreads();
    for (int s = 128; s > 0; s >>= 1) {
        if (t < s) red[t] = fmaxf(red[t], red[t + s]);
        __syncthreads();
    }
    vmax = red[0]; __syncthreads();
    float sum = 0.f;
#pragma unroll
    for (int j = 0; j < 8; j++) {
        v[j] = __expf(v[j] - vmax);
        sum += v[j];
    }
    red[t] = sum; __syncthreads();
    for (int s = 128; s > 0; s >>= 1) {
        if (t < s) red[t] += red[t + s];
        __syncthreads();
    }
    float inv = 1.0f / red[0];
#pragma unroll
    for (int j = 0; j < 8; j++)
        out[b * 2048 + j * 256 + t] = v[j] * inv;
}

// ---------------------------------------------------------------------------
// kernel_launch — inputs: d_hidden, encoder_outputs, W1, b1, w2
// ---------------------------------------------------------------------------
extern "C" void kernel_launch(void* const* d_in, const int* in_sizes, int n_in,
                              void* d_out, int out_size) {
    const float* dh  = (const float*)d_in[0];  // (32, 2, 512)
    const float* enc = (const float*)d_in[1];  // (32, 2048, 512)
    const float* W1  = (const float*)d_in[2];  // (1536, 512)
    const float* b1  = (const float*)d_in[3];  // (512,)
    const float* w2  = (const float*)d_in[4];  // (512,)
    float* out = (float*)d_out;                // (32, 2048)

    cudaFuncSetAttribute(attn_main_kernel, cudaFuncAttributeMaxDynamicSharedMemorySize,
                         (int)SMEM_MAIN);

    w1t_transpose_kernel<<<dim3(16, 16), dim3(32, 8)>>>(W1);
    dec_proj_kernel<<<128, 512>>>(dh, W1);
    attn_main_kernel<<<512, 256, SMEM_MAIN>>>(enc, b1, w2);
    softmax_kernel<<<32, 256>>>(out);
}

// round 3
// speedup vs baseline: 1.7353x; 1.7353x over previous
#include <cuda_runtime.h>
#include <cuda_bf16.h>
#include <cstdint>

// ============================================================================
// scores[b,l] = sum_d tanh( (enc[b,l,:] @ W1_e)[d] + dec_proj[b,d] + b1[d] ) * w2[d]
// out = softmax(scores, axis=-1).  B=32, LIN=2048, E=D=512, nd=1024.
//
// Plain sm_103 target (no tcgen05) -> bf16 mma.sync.m16n8k16 GEMM with
// ldmatrix fragment loads, 4-stage cp.async pipeline, fused tanh+dot epilogue.
// enc and W1_e^T are pre-converted to bf16 in gmem (error budget: tf32 run
// measured 4.7e-5; bf16 ~4x -> ~2e-4 << 1e-3).
// ============================================================================

// Scratch device globals (no allocation allowed)
__device__ __align__(16) __nv_bfloat16 g_encb[65536u * 512u]; // 64 MB bf16 A
__device__ __align__(16) __nv_bfloat16 g_W1Tb[512 * 512];     // W1_e^T bf16 [d][k]
__device__ __align__(16) float g_dpp[128 * 512];              // dec_proj split-K partials
__device__ __align__(16) float g_scores[32 * 2048];           // pre-softmax scores

// ---------------------------------------------------------------------------
// helpers
// ---------------------------------------------------------------------------
__device__ __forceinline__ uint32_t smem_u32(const void* p) {
    uint32_t a;
    asm("{ .reg .u64 t; cvta.to.shared.u64 t, %1; cvt.u32.u64 %0, t; }" : "=r"(a) : "l"(p));
    return a;
}
__device__ __forceinline__ void cp_async16(uint32_t sdst, const void* gsrc) {
    asm volatile("cp.async.cg.shared.global [%0], [%1], 16;" :: "r"(sdst), "l"(gsrc) : "memory");
}
#define CP_COMMIT() asm volatile("cp.async.commit_group;" ::: "memory")
#define CP_WAIT(n)  asm volatile("cp.async.wait_group %0;" :: "n"(n) : "memory")

__device__ __forceinline__ float tanh_fast(float x) {
    float t;
    asm("tanh.approx.f32 %0, %1;" : "=f"(t) : "f"(x));
    return t;
}
__device__ __forceinline__ void ldmatrix_x4(uint32_t r[4], uint32_t addr) {
    asm volatile("ldmatrix.sync.aligned.m8n8.x4.shared.b16 {%0,%1,%2,%3}, [%4];"
                 : "=r"(r[0]), "=r"(r[1]), "=r"(r[2]), "=r"(r[3]) : "r"(addr));
}
__device__ __forceinline__ void mma_bf16(float c[4], const uint32_t a[4], const uint32_t b[2]) {
    asm volatile(
        "mma.sync.aligned.m16n8k16.row.col.f32.bf16.bf16.f32 "
        "{%0,%1,%2,%3}, {%4,%5,%6,%7}, {%8,%9}, {%0,%1,%2,%3};"
        : "+f"(c[0]), "+f"(c[1]), "+f"(c[2]), "+f"(c[3])
        : "r"(a[0]), "r"(a[1]), "r"(a[2]), "r"(a[3]), "r"(b[0]), "r"(b[1]));
}

// ---------------------------------------------------------------------------
// Kernel A: convert enc fp32 -> bf16 (rn). 8 floats per thread.
// ---------------------------------------------------------------------------
__global__ void conv_enc_kernel(const float* __restrict__ enc) {
    size_t i = ((size_t)blockIdx.x * 256 + threadIdx.x) * 8;
    float4 a = *(const float4*)(enc + i);
    float4 b = *(const float4*)(enc + i + 4);
    __nv_bfloat162 p0 = __float22bfloat162_rn({a.x, a.y});
    __nv_bfloat162 p1 = __float22bfloat162_rn({a.z, a.w});
    __nv_bfloat162 p2 = __float22bfloat162_rn({b.x, b.y});
    __nv_bfloat162 p3 = __float22bfloat162_rn({b.z, b.w});
    uint4 o;
    o.x = *(uint32_t*)&p0; o.y = *(uint32_t*)&p1;
    o.z = *(uint32_t*)&p2; o.w = *(uint32_t*)&p3;
    *(uint4*)(g_encb + i) = o;
}

// ---------------------------------------------------------------------------
// Kernel B: transpose W1_e (rows 1024..1535 of W1, [512k x 512d]) -> bf16 [d][k]
// ---------------------------------------------------------------------------
__global__ void w1t_transpose_kernel(const float* __restrict__ W1) {
    __shared__ float tile[32][33];
    int tx = threadIdx.x, ty = threadIdx.y;
    int d0 = blockIdx.x * 32, k0 = blockIdx.y * 32;
#pragma unroll
    for (int j = 0; j < 32; j += 8)
        tile[ty + j][tx] = W1[(size_t)(1024 + k0 + ty + j) * 512 + d0 + tx];
    __syncthreads();
#pragma unroll
    for (int j = 0; j < 32; j += 8)
        g_W1Tb[(size_t)(d0 + ty + j) * 512 + k0 + tx] = __float2bfloat16_rn(tile[tx][ty + j]);
}

// ---------------------------------------------------------------------------
// Kernel C: dec_proj split-K partials (fp32 exact). block = b*4+q, 512 thr = d.
// ---------------------------------------------------------------------------
__global__ void dec_proj_kernel(const float* __restrict__ dh, const float* __restrict__ W1) {
    __shared__ float sdf[256];
    int bq = blockIdx.x;
    int b = bq >> 2, q = bq & 3;
    int d = threadIdx.x;
    if (d < 256) sdf[d] = dh[b * 1024 + q * 256 + d];
    __syncthreads();
    const float* w = W1 + (size_t)(q * 256) * 512 + d;
    float a0 = 0.f, a1 = 0.f, a2 = 0.f, a3 = 0.f;
#pragma unroll 4
    for (int k = 0; k < 256; k += 4) {
        a0 = fmaf(sdf[k + 0], w[(size_t)(k + 0) * 512], a0);
        a1 = fmaf(sdf[k + 1], w[(size_t)(k + 1) * 512], a1);
        a2 = fmaf(sdf[k + 2], w[(size_t)(k + 2) * 512], a2);
        a3 = fmaf(sdf[k + 3], w[(size_t)(k + 3) * 512], a3);
    }
    g_dpp[(size_t)bq * 512 + d] = (a0 + a1) + (a2 + a3);
}

// ---------------------------------------------------------------------------
// Kernel D: fused bf16 GEMM + tanh + dot(w2).
// 512 CTAs x 256 thr (8 warps: 2m x 4n, warp tile 64x64).
// CTA = 128 rows x 512 cols (2 n-passes of 256); K = 8 tiles of 64.
// Stage: A 128x64 bf16 (16KB, SW128) + B 256x64 bf16 (32KB, SW128). 4 stages.
// ---------------------------------------------------------------------------
static constexpr uint32_t AUX_SZ   = 8192;
static constexpr uint32_t STAGE_SZ = 49152;                  // 16KB A + 32KB B
static constexpr uint32_t SMEM_MAIN = AUX_SZ + 4 * STAGE_SZ; // 204800

__global__ void __launch_bounds__(256, 1)
attn_main_kernel(const float* __restrict__ b1, const float* __restrict__ w2) {
    extern __shared__ char sm[];
    float* add_s = (float*)sm;                 // 512 f
    float* w2_s  = (float*)(sm + 2048);        // 512 f
    float* spart = (float*)(sm + 4096);        // 4 x 128 f
    float* ssum  = (float*)(sm + 6144);        // 128 f
    char*  stages = sm + AUX_SZ;
    const uint32_t stages_u = smem_u32(stages);

    const int tid  = threadIdx.x;
    const int wid  = tid >> 5, lane = tid & 31;
    const int wm   = wid & 1, wn = wid >> 1;   // 2m x 4n warp grid
    const int quad = lane >> 2, qlane = lane & 3;
    const int lane7 = lane & 7;

    const int b  = blockIdx.x >> 4;
    const int l0 = (blockIdx.x & 15) << 7;
    const size_t row0 = (size_t)(b * 2048 + l0);
    const __nv_bfloat16* gA = g_encb + row0 * 512;

    for (int d = tid; d < 512; d += 256) {
        float s0 = g_dpp[(size_t)(b * 4 + 0) * 512 + d] + g_dpp[(size_t)(b * 4 + 1) * 512 + d];
        float s1 = g_dpp[(size_t)(b * 4 + 2) * 512 + d] + g_dpp[(size_t)(b * 4 + 3) * 512 + d];
        add_s[d] = s0 + s1 + b1[d];
        w2_s[d]  = w2[d];
    }
    if (tid < 128) ssum[tid] = 0.f;
    __syncthreads();

    // ---- prefetch: tile i -> np=i>>3, kt=i&7, stage=i&3 ----
    auto prefetch = [&](int i) {
        int np = i >> 3, kt = i & 7;
        uint32_t sA = stages_u + (uint32_t)(i & 3) * STAGE_SZ;
        uint32_t sB = sA + 16384;
        const __nv_bfloat16* srcA = gA + kt * 64;
        const __nv_bfloat16* srcB = g_W1Tb + (size_t)(np * 256) * 512 + kt * 64;
#pragma unroll
        for (int p = 0; p < 4; p++) {          // A: 128 rows x 128B
            int slot = tid + p * 256;
            int r = slot >> 3, blk = slot & 7;
            cp_async16(sA + (uint32_t)(r * 128 + ((blk ^ (r & 7)) << 4)),
                       srcA + (size_t)r * 512 + blk * 8);
        }
#pragma unroll
        for (int p = 0; p < 8; p++) {          // B: 256 rows x 128B
            int slot = tid + p * 256;
            int r = slot >> 3, blk = slot & 7;
            cp_async16(sB + (uint32_t)(r * 128 + ((blk ^ (r & 7)) << 4)),
                       srcB + (size_t)r * 512 + blk * 8);
        }
        CP_COMMIT();
    };

    prefetch(0); prefetch(1); prefetch(2);

    float acc[4][8][4];
#pragma unroll
    for (int mf = 0; mf < 4; mf++)
#pragma unroll
        for (int nf = 0; nf < 8; nf++)
#pragma unroll
            for (int k = 0; k < 4; k++) acc[mf][nf][k] = 0.f;

    // ldmatrix per-lane row offsets (row&7 == lane7 in all cases)
    const uint32_t a_row = (uint32_t)(wm * 64 + ((lane >> 3) & 1) * 8 + lane7);
    const uint32_t b_row = (uint32_t)(wn * 64 + (lane >> 4) * 8 + lane7);

    for (int i = 0; i < 16; i++) {
        CP_WAIT(2);
        __syncthreads();
        uint32_t sA = stages_u + (uint32_t)(i & 3) * STAGE_SZ;
        uint32_t sB = sA + 16384;

#pragma unroll
        for (int kf = 0; kf < 4; kf++) {
            uint32_t afr[4][4], bfr[8][2];
            uint32_t ablk = (uint32_t)(((kf * 2 + (lane >> 4)) ^ lane7) << 4);
            uint32_t bblk = (uint32_t)(((kf * 2 + ((lane >> 3) & 1)) ^ lane7) << 4);
#pragma unroll
            for (int mf = 0; mf < 4; mf++)
                ldmatrix_x4(afr[mf], sA + (a_row + mf * 16) * 128 + ablk);
#pragma unroll
            for (int j = 0; j < 4; j++) {
                uint32_t r[4];
                ldmatrix_x4(r, sB + (b_row + j * 16) * 128 + bblk);
                bfr[2 * j][0] = r[0]; bfr[2 * j][1] = r[1];
                bfr[2 * j + 1][0] = r[2]; bfr[2 * j + 1][1] = r[3];
            }
#pragma unroll
            for (int mf = 0; mf < 4; mf++)
#pragma unroll
                for (int nf = 0; nf < 8; nf++)
                    mma_bf16(acc[mf][nf], afr[mf], bfr[nf]);
        }

        if (i + 3 < 16) prefetch(i + 3);
        else CP_COMMIT();                       // keep group accounting uniform

        if ((i & 7) == 7) {
            // ---- epilogue for n-pass np: tanh(acc+add)*w2, row-reduce ----
            int np = i >> 3;
#pragma unroll
            for (int mf = 0; mf < 4; mf++) {
                float s0 = 0.f, s1 = 0.f;
#pragma unroll
                for (int nf = 0; nf < 8; nf++) {
                    int c = np * 256 + wn * 64 + nf * 8 + qlane * 2;
                    float a0 = add_s[c], a1 = add_s[c + 1];
                    float v0 = w2_s[c],  v1 = w2_s[c + 1];
                    s0 = fmaf(tanh_fast(acc[mf][nf][0] + a0), v0, s0);
                    s0 = fmaf(tanh_fast(acc[mf][nf][1] + a1), v1, s0);
                    s1 = fmaf(tanh_fast(acc[mf][nf][2] + a0), v0, s1);
                    s1 = fmaf(tanh_fast(acc[mf][nf][3] + a1), v1, s1);
                    acc[mf][nf][0] = 0.f; acc[mf][nf][1] = 0.f;
                    acc[mf][nf][2] = 0.f; acc[mf][nf][3] = 0.f;
                }
                s0 += __shfl_xor_sync(0xffffffffu, s0, 1);
                s0 += __shfl_xor_sync(0xffffffffu, s0, 2);
                s1 += __shfl_xor_sync(0xffffffffu, s1, 1);
                s1 += __shfl_xor_sync(0xffffffffu, s1, 2);
                if (qlane == 0) {
                    int r = wm * 64 + mf * 16 + quad;
                    spart[wn * 128 + r]     = s0;
                    spart[wn * 128 + r + 8] = s1;
                }
            }
            __syncthreads();
            if (tid < 128)
                ssum[tid] += spart[tid] + spart[128 + tid] + spart[256 + tid] + spart[384 + tid];
            __syncthreads();
        }
    }

    if (tid < 128) g_scores[row0 + tid] = ssum[tid];
}

// ---------------------------------------------------------------------------
// Kernel E: row softmax over 2048. 32 blocks x 256 threads.
// ---------------------------------------------------------------------------
__global__ void softmax_kernel(float* __restrict__ out) {
    __shared__ float red[256];
    int b = blockIdx.x, t = threadIdx.x;
    float v[8];
    float vmax = -1e30f;
#pragma unroll
    for (int j = 0; j < 8; j++) {
        v[j] = g_scores[b * 2048 + j * 256 + t];
        vmax = fmaxf(vmax, v[j]);
    }
    red[t] = vmax; __syncthreads();
    for (int s = 128; s > 0; s >>= 1) {
        if (t < s) red[t] = fmaxf(red[t], red[t + s]);
        __syncthreads();
    }
    vmax = red[0]; __syncthreads();
    float sum = 0.f;
#pragma unroll
    for (int j = 0; j < 8; j++) {
        v[j] = __expf(v[j] - vmax);
        sum += v[j];
    }
    red[t] = sum; __syncthreads();
    for (int s = 128; s > 0; s >>= 1) {
        if (t < s) red[t] += red[t + s];
        __syncthreads();
    }
    float inv = 1.0f / red[0];
#pragma unroll
    for (int j = 0; j < 8; j++)
        out[b * 2048 + j * 256 + t] = v[j] * inv;
}

// ---------------------------------------------------------------------------
// kernel_launch — inputs: d_hidden, encoder_outputs, W1, b1, w2
// ---------------------------------------------------------------------------
extern "C" void kernel_launch(void* const* d_in, const int* in_sizes, int n_in,
                              void* d_out, int out_size) {
    const float* dh  = (const float*)d_in[0];  // (32, 2, 512)
    const float* enc = (const float*)d_in[1];  // (32, 2048, 512)
    const float* W1  = (const float*)d_in[2];  // (1536, 512)
    const float* b1  = (const float*)d_in[3];  // (512,)
    const float* w2  = (const float*)d_in[4];  // (512,)
    float* out = (float*)d_out;                // (32, 2048)

    cudaFuncSetAttribute(attn_main_kernel, cudaFuncAttributeMaxDynamicSharedMemorySize,
                         (int)SMEM_MAIN);

    conv_enc_kernel<<<16384, 256>>>(enc);                 // 65536*512 / (256*8)
    w1t_transpose_kernel<<<dim3(16, 16), dim3(32, 8)>>>(W1);
    dec_proj_kernel<<<128, 512>>>(dh, W1);
    attn_main_kernel<<<512, 256, SMEM_MAIN>>>(b1, w2);
    softmax_kernel<<<32, 256>>>(out);
}

// round 4
// speedup vs baseline: 1.9102x; 1.1008x over previous
#include <cuda_runtime.h>
#include <cuda_bf16.h>
#include <cstdint>

// ============================================================================
// scores[b,l] = sum_d tanh( (enc[b,l,:] @ W1_e)[d] + dec_proj[b,d] + b1[d] ) * w2[d]
// out = softmax(scores, axis=-1).  B=32, LIN=2048, E=D=512, nd=1024.
//
// bf16 mma.sync.m16n8k16 GEMM, fused tanh+dot(w2) epilogue.
// R4: occupancy-2 main kernel (units 128x128, acc 64 regs, 3-stage cp.async),
// deterministic per-column-unit partial scores, fused prep kernel.
// ============================================================================

// Scratch device globals (no allocation allowed)
__device__ __align__(16) __nv_bfloat16 g_encb[65536u * 512u]; // 64 MB bf16 A
__device__ __align__(16) __nv_bfloat16 g_W1Tb[512 * 512];     // W1_e^T bf16 [d][k]
__device__ __align__(16) float g_dpp[128 * 512];              // dec_proj split-K partials
__device__ __align__(16) float g_spart[4u * 65536u];          // per-colunit partial scores

// ---------------------------------------------------------------------------
// helpers
// ---------------------------------------------------------------------------
__device__ __forceinline__ uint32_t smem_u32(const void* p) {
    uint32_t a;
    asm("{ .reg .u64 t; cvta.to.shared.u64 t, %1; cvt.u32.u64 %0, t; }" : "=r"(a) : "l"(p));
    return a;
}
__device__ __forceinline__ void cp_async16(uint32_t sdst, const void* gsrc) {
    asm volatile("cp.async.cg.shared.global [%0], [%1], 16;" :: "r"(sdst), "l"(gsrc) : "memory");
}
#define CP_COMMIT() asm volatile("cp.async.commit_group;" ::: "memory")
#define CP_WAIT(n)  asm volatile("cp.async.wait_group %0;" :: "n"(n) : "memory")

__device__ __forceinline__ float tanh_fast(float x) {
    float t;
    asm("tanh.approx.f32 %0, %1;" : "=f"(t) : "f"(x));
    return t;
}
__device__ __forceinline__ void ldmatrix_x4(uint32_t r[4], uint32_t addr) {
    asm volatile("ldmatrix.sync.aligned.m8n8.x4.shared.b16 {%0,%1,%2,%3}, [%4];"
                 : "=r"(r[0]), "=r"(r[1]), "=r"(r[2]), "=r"(r[3]) : "r"(addr));
}
__device__ __forceinline__ void mma_bf16(float c[4], const uint32_t a[4], const uint32_t b[2]) {
    asm volatile(
        "mma.sync.aligned.m16n8k16.row.col.f32.bf16.bf16.f32 "
        "{%0,%1,%2,%3}, {%4,%5,%6,%7}, {%8,%9}, {%0,%1,%2,%3};"
        : "+f"(c[0]), "+f"(c[1]), "+f"(c[2]), "+f"(c[3])
        : "r"(a[0]), "r"(a[1]), "r"(a[2]), "r"(a[3]), "r"(b[0]), "r"(b[1]));
}

// ---------------------------------------------------------------------------
// Kernel P: fused prep. blocks [0,16384): enc fp32->bf16;
//           [16384,16640): W1_e transpose->bf16; [16640,16768): dec_proj.
// ---------------------------------------------------------------------------
__global__ void prep_kernel(const float* __restrict__ enc, const float* __restrict__ W1,
                            const float* __restrict__ dh) {
    int bid = blockIdx.x, tid = threadIdx.x;
    if (bid < 16384) {
        size_t i = ((size_t)bid * 256 + tid) * 8;
        float4 a = *(const float4*)(enc + i);
        float4 b = *(const float4*)(enc + i + 4);
        __nv_bfloat162 p0 = __float22bfloat162_rn({a.x, a.y});
        __nv_bfloat162 p1 = __float22bfloat162_rn({a.z, a.w});
        __nv_bfloat162 p2 = __float22bfloat162_rn({b.x, b.y});
        __nv_bfloat162 p3 = __float22bfloat162_rn({b.z, b.w});
        uint4 o;
        o.x = *(uint32_t*)&p0; o.y = *(uint32_t*)&p1;
        o.z = *(uint32_t*)&p2; o.w = *(uint32_t*)&p3;
        *(uint4*)(g_encb + i) = o;
    } else if (bid < 16640) {
        __shared__ float tile[32][33];
        int v = bid - 16384;
        int d0 = (v & 15) * 32, k0 = (v >> 4) * 32;
        int tx = tid & 31, ty = tid >> 5;
#pragma unroll
        for (int j = 0; j < 32; j += 8)
            tile[ty + j][tx] = W1[(size_t)(1024 + k0 + ty + j) * 512 + d0 + tx];
        __syncthreads();
#pragma unroll
        for (int j = 0; j < 32; j += 8)
            g_W1Tb[(size_t)(d0 + ty + j) * 512 + k0 + tx] = __float2bfloat16_rn(tile[tx][ty + j]);
    } else {
        __shared__ float sdf[256];
        int bq = bid - 16640;
        int b = bq >> 2, q = bq & 3;
        sdf[tid] = dh[b * 1024 + q * 256 + tid];
        __syncthreads();
        // each thread computes 2 d's: tid and tid+256
        const float* w0 = W1 + (size_t)(q * 256) * 512 + tid;
        const float* w1 = w0 + 256;
        float a0 = 0.f, a1 = 0.f, b0 = 0.f, b1v = 0.f;
#pragma unroll 4
        for (int k = 0; k < 256; k += 2) {
            a0  = fmaf(sdf[k],     w0[(size_t)k * 512],       a0);
            a1  = fmaf(sdf[k + 1], w0[(size_t)(k + 1) * 512], a1);
            b0  = fmaf(sdf[k],     w1[(size_t)k * 512],       b0);
            b1v = fmaf(sdf[k + 1], w1[(size_t)(k + 1) * 512], b1v);
        }
        g_dpp[(size_t)bq * 512 + tid]       = a0 + a1;
        g_dpp[(size_t)bq * 512 + tid + 256] = b0 + b1v;
    }
}

// ---------------------------------------------------------------------------
// Kernel M: fused bf16 GEMM + tanh + dot(w2).
// Grid 2048 units: bid = rowchunk*4 + colunit (colunit inner -> A L2 reuse).
// Unit = 128 rows x 128 cols. 8 warps (2m x 4n), warp tile 64x32, acc 64 regs.
// K = 8 tiles of 64; 3 stages x (A 16KB + B 16KB); occupancy 2.
// ---------------------------------------------------------------------------
static constexpr uint32_t AUX_SZ   = 4096;
static constexpr uint32_t STAGE_SZ = 32768;                  // A 16KB + B 16KB
static constexpr uint32_t SMEM_MAIN = AUX_SZ + 3 * STAGE_SZ; // 102400

__global__ void __launch_bounds__(256, 2)
attn_main_kernel(const float* __restrict__ b1, const float* __restrict__ w2) {
    extern __shared__ char sm[];
    float* add_s = (float*)sm;                 // 128 f
    float* w2_s  = (float*)(sm + 512);         // 128 f
    float* spart = (float*)(sm + 1024);        // 4 x 128 f
    const uint32_t stages_u = smem_u32(sm + AUX_SZ);

    const int tid  = threadIdx.x;
    const int lane = tid & 31, wid = tid >> 5;
    const int wm   = wid & 1, wn = wid >> 1;   // 2m x 4n warp grid
    const int quad = lane >> 2, qlane = lane & 3;
    const int lane7 = lane & 7;

    const int cu = blockIdx.x & 3;             // column unit (inner -> L2 A reuse)
    const int rc = blockIdx.x >> 2;            // row chunk 0..511
    const size_t row0 = (size_t)rc * 128;
    const __nv_bfloat16* gA = g_encb + row0 * 512;
    const __nv_bfloat16* gB = g_W1Tb + (size_t)(cu * 128) * 512;

    const int b = rc >> 4;                     // batch for dec_proj
    if (tid < 128) {
        int d = cu * 128 + tid;
        float s0 = g_dpp[(size_t)(b * 4 + 0) * 512 + d] + g_dpp[(size_t)(b * 4 + 1) * 512 + d];
        float s1 = g_dpp[(size_t)(b * 4 + 2) * 512 + d] + g_dpp[(size_t)(b * 4 + 3) * 512 + d];
        add_s[tid] = s0 + s1 + b1[d];
        w2_s[tid]  = w2[d];
    }

    // prefetch k-tile t into stage t%3 (A and B are both 128 rows x 128B)
    auto prefetch = [&](int t) {
        uint32_t sA = stages_u + (uint32_t)(t % 3) * STAGE_SZ;
        uint32_t sB = sA + 16384;
        const __nv_bfloat16* srcA = gA + t * 64;
        const __nv_bfloat16* srcB = gB + t * 64;
#pragma unroll
        for (int p = 0; p < 4; p++) {
            int slot = tid + p * 256;
            int r = slot >> 3, blk = slot & 7;
            uint32_t off = (uint32_t)(r * 128 + ((blk ^ (r & 7)) << 4));
            cp_async16(sA + off, srcA + (size_t)r * 512 + blk * 8);
            cp_async16(sB + off, srcB + (size_t)r * 512 + blk * 8);
        }
        CP_COMMIT();
    };

    prefetch(0); prefetch(1);

    float acc[4][4][4];
#pragma unroll
    for (int mf = 0; mf < 4; mf++)
#pragma unroll
        for (int nf = 0; nf < 4; nf++)
#pragma unroll
            for (int k = 0; k < 4; k++) acc[mf][nf][k] = 0.f;

    const uint32_t a_row = (uint32_t)(wm * 64 + ((lane >> 3) & 1) * 8 + lane7);
    const uint32_t b_row = (uint32_t)(wn * 32 + (lane >> 4) * 8 + lane7);

    for (int i = 0; i < 8; i++) {
        CP_WAIT(1);
        __syncthreads();
        uint32_t sA = stages_u + (uint32_t)(i % 3) * STAGE_SZ;
        uint32_t sB = sA + 16384;

#pragma unroll
        for (int kf = 0; kf < 4; kf++) {
            uint32_t afr[4][4], bfr[4][2];
            uint32_t ablk = (uint32_t)(((kf * 2 + (lane >> 4)) ^ lane7) << 4);
            uint32_t bblk = (uint32_t)(((kf * 2 + ((lane >> 3) & 1)) ^ lane7) << 4);
#pragma unroll
            for (int mf = 0; mf < 4; mf++)
                ldmatrix_x4(afr[mf], sA + (a_row + mf * 16) * 128 + ablk);
#pragma unroll
            for (int j = 0; j < 2; j++) {
                uint32_t r[4];
                ldmatrix_x4(r, sB + (b_row + j * 16) * 128 + bblk);
                bfr[2 * j][0] = r[0];     bfr[2 * j][1] = r[1];
                bfr[2 * j + 1][0] = r[2]; bfr[2 * j + 1][1] = r[3];
            }
#pragma unroll
            for (int mf = 0; mf < 4; mf++)
#pragma unroll
                for (int nf = 0; nf < 4; nf++)
                    mma_bf16(acc[mf][nf], afr[mf], bfr[nf]);
        }

        if (i + 2 < 8) prefetch(i + 2);
        else CP_COMMIT();                      // keep group accounting uniform
    }

    // ---- epilogue: tanh(acc + add) * w2, reduce over 128 cols ----
#pragma unroll
    for (int mf = 0; mf < 4; mf++) {
        float s0 = 0.f, s1 = 0.f;
#pragma unroll
        for (int nf = 0; nf < 4; nf++) {
            int c = wn * 32 + nf * 8 + qlane * 2;
            float a0 = add_s[c], a1 = add_s[c + 1];
            float v0 = w2_s[c],  v1 = w2_s[c + 1];
            s0 = fmaf(tanh_fast(acc[mf][nf][0] + a0), v0, s0);
            s0 = fmaf(tanh_fast(acc[mf][nf][1] + a1), v1, s0);
            s1 = fmaf(tanh_fast(acc[mf][nf][2] + a0), v0, s1);
            s1 = fmaf(tanh_fast(acc[mf][nf][3] + a1), v1, s1);
        }
        s0 += __shfl_xor_sync(0xffffffffu, s0, 1);
        s0 += __shfl_xor_sync(0xffffffffu, s0, 2);
        s1 += __shfl_xor_sync(0xffffffffu, s1, 1);
        s1 += __shfl_xor_sync(0xffffffffu, s1, 2);
        if (qlane == 0) {
            int r = wm * 64 + mf * 16 + quad;
            spart[wn * 128 + r]     = s0;
            spart[wn * 128 + r + 8] = s1;
        }
    }
    __syncthreads();
    if (tid < 128)
        g_spart[(size_t)cu * 65536 + row0 + tid] =
            spart[tid] + spart[128 + tid] + spart[256 + tid] + spart[384 + tid];
}

// ---------------------------------------------------------------------------
// Kernel S: sum 4 partials + row softmax over 2048. 32 blocks x 256 threads.
// ---------------------------------------------------------------------------
__global__ void softmax_kernel(float* __restrict__ out) {
    __shared__ float red[256];
    int b = blockIdx.x, t = threadIdx.x;
    float v[8];
    float vmax = -1e30f;
#pragma unroll
    for (int j = 0; j < 8; j++) {
        size_t idx = (size_t)b * 2048 + j * 256 + t;
        v[j] = g_spart[idx] + g_spart[65536 + idx] + g_spart[131072 + idx] + g_spart[196608 + idx];
        vmax = fmaxf(vmax, v[j]);
    }
    red[t] = vmax; __syncthreads();
    for (int s = 128; s > 0; s >>= 1) {
        if (t < s) red[t] = fmaxf(red[t], red[t + s]);
        __syncthreads();
    }
    vmax = red[0]; __syncthreads();
    float sum = 0.f;
#pragma unroll
    for (int j = 0; j < 8; j++) {
        v[j] = __expf(v[j] - vmax);
        sum += v[j];
    }
    red[t] = sum; __syncthreads();
    for (int s = 128; s > 0; s >>= 1) {
        if (t < s) red[t] += red[t + s];
        __syncthreads();
    }
    float inv = 1.0f / red[0];
#pragma unroll
    for (int j = 0; j < 8; j++)
        out[b * 2048 + j * 256 + t] = v[j] * inv;
}

// ---------------------------------------------------------------------------
// kernel_launch — inputs: d_hidden, encoder_outputs, W1, b1, w2
// ---------------------------------------------------------------------------
extern "C" void kernel_launch(void* const* d_in, const int* in_sizes, int n_in,
                              void* d_out, int out_size) {
    const float* dh  = (const float*)d_in[0];  // (32, 2, 512)
    const float* enc = (const float*)d_in[1];  // (32, 2048, 512)
    const float* W1  = (const float*)d_in[2];  // (1536, 512)
    const float* b1  = (const float*)d_in[3];  // (512,)
    const float* w2  = (const float*)d_in[4];  // (512,)
    float* out = (float*)d_out;                // (32, 2048)

    cudaFuncSetAttribute(attn_main_kernel, cudaFuncAttributeMaxDynamicSharedMemorySize,
                         (int)SMEM_MAIN);

    prep_kernel<<<16768, 256>>>(enc, W1, dh);
    attn_main_kernel<<<2048, 256, SMEM_MAIN>>>(b1, w2);
    softmax_kernel<<<32, 256>>>(out);
}